// round 15
// baseline (speedup 1.0000x reference)
#include <cuda_runtime.h>
#include <cuda_bf16.h>
#include <cstdint>
#include <math.h>

// Problem shape (fixed)
#define BB 2
#define NN 2048
#define DD 1024
#define HH 16
#define HD 64
#define SCALE 0.125f   // HD^-0.5

// ---------------- scratch (no allocation allowed) ----------------
__device__ float g_q[(size_t)BB*HH*NN*HD];       // [b][h][n][hd]
__device__ float g_k[(size_t)BB*HH*NN*HD];
__device__ float g_v[(size_t)BB*HH*NN*HD];
__device__ float g_attnout[(size_t)BB*NN*DD];    // [b][n][d]
__device__ float g_bias[(size_t)BB*HH*NN];       // g * cov, [b][h][m]
__device__ float g_pooled[BB*DD];
__device__ float g_gate[BB];

// bf16 hi/lo split buffers (QKV GEMM only this round)
__device__ __nv_bfloat16 g_xa_hi[(size_t)BB*NN*DD];     // x as A [4096][1024]
__device__ __nv_bfloat16 g_xa_lo[(size_t)BB*NN*DD];
__device__ __nv_bfloat16 g_wqt_hi[(size_t)3*DD*DD];     // w_qkv^T [3072][1024]
__device__ __nv_bfloat16 g_wqt_lo[(size_t)3*DD*DD];

__device__ __forceinline__ uint32_t smem_u32(const void* p) {
    uint32_t a;
    asm("{ .reg .u64 t; cvta.to.shared.u64 t, %1; cvt.u32.u64 %0, t; }"
        : "=r"(a) : "l"(p));
    return a;
}

// ---------------- tiny kernels ----------------
__global__ void zero_pooled_kernel() {
    int i = blockIdx.x * blockDim.x + threadIdx.x;
    if (i < BB*DD) g_pooled[i] = 0.f;
}

__global__ void pool_kernel(const float* __restrict__ x) {
    int b = blockIdx.y;
    int d = blockIdx.x * blockDim.x + threadIdx.x;
    int n0 = blockIdx.z * 128;
    const float* xp = x + ((size_t)b*NN + n0)*DD + d;
    float s = 0.f;
    #pragma unroll 4
    for (int n = 0; n < 128; n++) s += xp[(size_t)n*DD];
    atomicAdd(&g_pooled[b*DD + d], s * (1.0f/NN));
}

__global__ void gate_kernel(const float* __restrict__ w_fg1, const float* __restrict__ b_fg1,
                            const float* __restrict__ w_fg2, const float* __restrict__ b_fg2) {
    int b = blockIdx.x;
    int j = threadIdx.x;   // 256
    const float* p = g_pooled + b*DD;
    float acc = b_fg1[j];
    #pragma unroll 4
    for (int k = 0; k < DD; k++) acc += p[k] * w_fg1[k*256 + j];
    float hid = acc / (1.f + __expf(-acc));   // silu
    float part = hid * w_fg2[j];
    __shared__ float red[256];
    red[j] = part;
    __syncthreads();
    for (int s = 128; s > 0; s >>= 1) {
        if (j < s) red[j] += red[j + s];
        __syncthreads();
    }
    if (j == 0) g_gate[b] = 1.f / (1.f + __expf(-(red[0] + b_fg2[0])));
}

// coverage MLP with smem-cached weights, 8 tokens per block (warp each)
__global__ __launch_bounds__(256) void cov_kernel3(
    const float* __restrict__ coverage,
    const float* __restrict__ w_ce1, const float* __restrict__ b_ce1,
    const float* __restrict__ w_ce2, const float* __restrict__ b_ce2) {
    __shared__ float s_w1[256], s_b1[256], s_w2[256*17];
    int tid = threadIdx.x;
    s_w1[tid] = w_ce1[tid];
    s_b1[tid] = b_ce1[tid];
    #pragma unroll
    for (int i = 0; i < 16; i++) {
        int idx = tid + 256*i;
        s_w2[(idx >> 4)*17 + (idx & 15)] = w_ce2[idx];
    }
    __syncthreads();
    int w = tid >> 5, lane = tid & 31;
    int m = blockIdx.x * 8 + w;
    int b = blockIdx.y;
    float c = coverage[b*NN + m];
    float g = g_gate[b];
    float acc[HH];
    #pragma unroll
    for (int h = 0; h < HH; h++) acc[h] = 0.f;
    #pragma unroll
    for (int t = 0; t < 8; t++) {
        int j = lane + 32*t;
        float tt = fmaf(c, s_w1[j], s_b1[j]);
        float hid = tt / (1.f + __expf(-tt));
        #pragma unroll
        for (int h = 0; h < HH; h++)
            acc[h] = fmaf(hid, s_w2[j*17 + h], acc[h]);
    }
    #pragma unroll
    for (int mask = 16; mask >= 1; mask >>= 1)
        #pragma unroll
        for (int h = 0; h < HH; h++)
            acc[h] += __shfl_xor_sync(0xffffffffu, acc[h], mask);
    if (lane < HH)
        g_bias[((size_t)b*HH + lane)*NN + m] = g * (acc[lane] + b_ce2[lane]);
}

// ---------------- fp32 -> bf16 hi/lo split ----------------
__global__ __launch_bounds__(256) void split_kernel(
    const float* __restrict__ src, __nv_bfloat16* __restrict__ hi,
    __nv_bfloat16* __restrict__ lo) {
    int i = blockIdx.x * blockDim.x + threadIdx.x;   // float4 index
    float4 v = ((const float4*)src)[i];
    __nv_bfloat16 h0 = __float2bfloat16(v.x), h1 = __float2bfloat16(v.y);
    __nv_bfloat16 h2 = __float2bfloat16(v.z), h3 = __float2bfloat16(v.w);
    __nv_bfloat162* hp = (__nv_bfloat162*)hi;
    __nv_bfloat162* lp = (__nv_bfloat162*)lo;
    hp[2*i]   = __nv_bfloat162(h0, h1);
    hp[2*i+1] = __nv_bfloat162(h2, h3);
    __nv_bfloat16 l0 = __float2bfloat16(v.x - __bfloat162float(h0));
    __nv_bfloat16 l1 = __float2bfloat16(v.y - __bfloat162float(h1));
    __nv_bfloat16 l2 = __float2bfloat16(v.z - __bfloat162float(h2));
    __nv_bfloat16 l3 = __float2bfloat16(v.w - __bfloat162float(h3));
    lp[2*i]   = __nv_bfloat162(l0, l1);
    lp[2*i+1] = __nv_bfloat162(l2, l3);
}

// transpose [R][C] f32 -> [C][R] bf16 hi/lo
__global__ __launch_bounds__(256) void tsplit_kernel(
    const float* __restrict__ src, __nv_bfloat16* __restrict__ dhi,
    __nv_bfloat16* __restrict__ dlo, int R, int C) {
    __shared__ float t[32][33];
    int tx = threadIdx.x, ty = threadIdx.y;   // (32, 8)
    int c0 = blockIdx.x * 32, r0 = blockIdx.y * 32;
    #pragma unroll
    for (int i = 0; i < 4; i++)
        t[ty + 8*i][tx] = src[(size_t)(r0 + ty + 8*i)*C + c0 + tx];
    __syncthreads();
    #pragma unroll
    for (int i = 0; i < 4; i++) {
        float v = t[tx][ty + 8*i];
        int orow = c0 + ty + 8*i, ocol = r0 + tx;
        __nv_bfloat16 h = __float2bfloat16(v);
        dhi[(size_t)orow*R + ocol] = h;
        dlo[(size_t)orow*R + ocol] = __float2bfloat16(v - __bfloat162float(h));
    }
}

// ---------------- QKV GEMM: mma.sync bf16, direct-LDS fragments (no ldmatrix) ----
// C[4096 x 3072] = A @ W^T, W stored [n][k]; hi/lo 3-pass K'=96 stages of BK=32.
// 256 thr; warp (wm=w&1, wn=w>>1) -> 64x32 warp tile; mma m16n8k16.
// smem swizzle: 16B chunk c' = c ^ ((r>>1)&3); fragment k-pairs contiguous.

__device__ __forceinline__ void mma16816(float* d, const uint32_t* a, const uint32_t* b) {
    asm volatile("mma.sync.aligned.m16n8k16.row.col.f32.bf16.bf16.f32 "
                 "{%0,%1,%2,%3}, {%4,%5,%6,%7}, {%8,%9}, {%0,%1,%2,%3};"
                 : "+f"(d[0]), "+f"(d[1]), "+f"(d[2]), "+f"(d[3])
                 : "r"(a[0]), "r"(a[1]), "r"(a[2]), "r"(a[3]), "r"(b[0]), "r"(b[1]));
}
// byte offset of element (row, k) inside one 128x32 bf16 tile with chunk swizzle
__device__ __forceinline__ int fragoff(int row, int k) {
    return row*64 + (((k >> 3) ^ ((row >> 1) & 3)) << 4) + (k & 7)*2;
}

__global__ __launch_bounds__(256) void hgemm_qkv(
    const __nv_bfloat16* __restrict__ Ahi, const __nv_bfloat16* __restrict__ Alo,
    const __nv_bfloat16* __restrict__ Bhi, const __nv_bfloat16* __restrict__ Blo)
{
    __shared__ __align__(16) __nv_bfloat16 sA[2][4096];
    __shared__ __align__(16) __nv_bfloat16 sB[2][4096];
    const char* sAb = (const char*)sA;
    const char* sBb = (const char*)sB;
    uint32_t aBase = smem_u32(sA), bBase = smem_u32(sB);

    int tid = threadIdx.x, w = tid >> 5, lane = tid & 31;
    int wm = w & 1, wn = w >> 1;
    int m0 = blockIdx.y * 128, n0 = blockIdx.x * 128;
    int q = lane >> 2, kp = (lane & 3)*2;   // fragment row-in-8 / k-pair base

    float acc[4][4][4];
    #pragma unroll
    for (int mi = 0; mi < 4; mi++)
        #pragma unroll
        for (int ni = 0; ni < 4; ni++)
            #pragma unroll
            for (int f = 0; f < 4; f++) acc[mi][ni][f] = 0.f;

    // stage s in [0,96): seg = s>>5 (0:hi*hi 1:lo*hi 2:hi*lo), kc = s&31.
    auto load_stage = [&](int s, int buf) {
        int seg = s >> 5, kc = s & 31;
        const __nv_bfloat16* Ap = (seg == 1) ? Alo : Ahi;
        const __nv_bfloat16* Bp = (seg == 2) ? Blo : Bhi;
        #pragma unroll
        for (int t = 0; t < 2; t++) {
            int idx = t*256 + tid;            // 512 x 16B chunks per array
            int r = idx >> 2, ch = idx & 3;
            uint32_t soff = (uint32_t)(buf*8192 + r*64 + ((ch ^ ((r>>1)&3)) << 4));
            const char* gpA = (const char*)(Ap + (size_t)(m0 + r)*DD + kc*32) + ch*16;
            asm volatile("cp.async.cg.shared.global [%0], [%1], 16;"
                         :: "r"(aBase + soff), "l"(gpA));
            const char* gpB = (const char*)(Bp + (size_t)(n0 + r)*DD + kc*32) + ch*16;
            asm volatile("cp.async.cg.shared.global [%0], [%1], 16;"
                         :: "r"(bBase + soff), "l"(gpB));
        }
        asm volatile("cp.async.commit_group;");
    };

    load_stage(0, 0);
    asm volatile("cp.async.wait_group 0;");
    __syncthreads();

    for (int s = 0; s < 96; s++) {
        int buf = s & 1;
        if (s < 95) load_stage(s + 1, buf ^ 1);
        int bufoff = buf*8192;

        #pragma unroll
        for (int kk = 0; kk < 2; kk++) {
            int kb = kk*16 + kp;
            uint32_t af[4][4], bfr[4][2];
            #pragma unroll
            for (int mi = 0; mi < 4; mi++) {
                int rr = wm*64 + mi*16 + q;
                af[mi][0] = *(const uint32_t*)(sAb + bufoff + fragoff(rr,     kb));
                af[mi][1] = *(const uint32_t*)(sAb + bufoff + fragoff(rr + 8, kb));
                af[mi][2] = *(const uint32_t*)(sAb + bufoff + fragoff(rr,     kb + 8));
                af[mi][3] = *(const uint32_t*)(sAb + bufoff + fragoff(rr + 8, kb + 8));
            }
            #pragma unroll
            for (int ni = 0; ni < 4; ni++) {
                int nr = wn*32 + ni*8 + q;
                bfr[ni][0] = *(const uint32_t*)(sBb + bufoff + fragoff(nr, kb));
                bfr[ni][1] = *(const uint32_t*)(sBb + bufoff + fragoff(nr, kb + 8));
            }
            #pragma unroll
            for (int mi = 0; mi < 4; mi++)
                #pragma unroll
                for (int ni = 0; ni < 4; ni++)
                    mma16816(acc[mi][ni], af[mi], bfr[ni]);
        }

        if (s < 95) asm volatile("cp.async.wait_group 0;");
        __syncthreads();
    }

    // epilogue: D frag rows q, q+8; cols kp, kp+1. Scatter into g_q/g_k/g_v.
    #pragma unroll
    for (int mi = 0; mi < 4; mi++) {
        #pragma unroll
        for (int ni = 0; ni < 4; ni++) {
            int r = m0 + wm*64 + mi*16 + q;
            int c = n0 + wn*32 + ni*8 + kp;
            int part = c >> 10, d = c & 1023;
            int h = d >> 6, hd = d & 63;
            float* dst = (part == 0) ? g_q : (part == 1) ? g_k : g_v;
            int b = r >> 11, n = r & 2047;
            size_t base = ((((size_t)b*HH + h)*NN + n) << 6) + hd;
            *(float2*)&dst[base] = make_float2(acc[mi][ni][0], acc[mi][ni][1]);
            int b2 = (r+8) >> 11, n2 = (r+8) & 2047;
            size_t base2 = ((((size_t)b2*HH + h)*NN + n2) << 6) + hd;
            *(float2*)&dst[base2] = make_float2(acc[mi][ni][2], acc[mi][ni][3]);
        }
    }
}

// ---------------- fp32 SGEMM out-projection (known-good from R3) ----------------
__global__ __launch_bounds__(256) void sgemm_out(
    const float* __restrict__ Bm, float* __restrict__ C,
    const float* __restrict__ bias)
{
    const int K = DD, Nn = DD;
    __shared__ __align__(16) float As[2][8][128];
    __shared__ __align__(16) float Bs[2][8][128];
    int tid = threadIdx.x;
    int m0 = blockIdx.y * 128;
    int n0 = blockIdx.x * 128;
    int ty = tid >> 4, tx = tid & 15;
    const float* Ap = g_attnout;

    float acc[8][8];
    #pragma unroll
    for (int i = 0; i < 8; i++)
        #pragma unroll
        for (int j = 0; j < 8; j++) acc[i][j] = 0.f;

    int arow = tid >> 1;
    int acol = (tid & 1) * 4;
    int brow = tid >> 5;
    int bcol = (tid & 31) * 4;
    const float* Aptr = Ap + (size_t)(m0 + arow)*K + acol;
    const float* Bptr = Bm + (size_t)brow*Nn + n0 + bcol;

    {
        float4 av = *(const float4*)(Aptr);
        float4 bv = *(const float4*)(Bptr);
        As[0][acol+0][arow] = av.x;
        As[0][acol+1][arow] = av.y;
        As[0][acol+2][arow] = av.z;
        As[0][acol+3][arow] = av.w;
        *(float4*)&Bs[0][brow][bcol] = bv;
    }
    __syncthreads();

    int buf = 0;
    for (int k0 = 0; k0 < K; k0 += 8) {
        float4 av, bv;
        bool more = (k0 + 8 < K);
        if (more) {
            av = *(const float4*)(Aptr + k0 + 8);
            bv = *(const float4*)(Bptr + (size_t)(k0 + 8)*Nn);
        }
        #pragma unroll
        for (int kk = 0; kk < 8; kk++) {
            float a[8], bb[8];
            *(float4*)&a[0] = *(const float4*)&As[buf][kk][ty*8];
            *(float4*)&a[4] = *(const float4*)&As[buf][kk][ty*8+4];
            *(float4*)&bb[0] = *(const float4*)&Bs[buf][kk][tx*8];
            *(float4*)&bb[4] = *(const float4*)&Bs[buf][kk][tx*8+4];
            #pragma unroll
            for (int i = 0; i < 8; i++)
                #pragma unroll
                for (int j = 0; j < 8; j++)
                    acc[i][j] = fmaf(a[i], bb[j], acc[i][j]);
        }
        if (more) {
            As[buf^1][acol+0][arow] = av.x;
            As[buf^1][acol+1][arow] = av.y;
            As[buf^1][acol+2][arow] = av.z;
            As[buf^1][acol+3][arow] = av.w;
            *(float4*)&Bs[buf^1][brow][bcol] = bv;
        }
        __syncthreads();
        buf ^= 1;
    }

    #pragma unroll
    for (int i = 0; i < 8; i++) {
        int r = m0 + ty*8 + i;
        float* Crow = C + (size_t)r*Nn;
        #pragma unroll
        for (int j = 0; j < 8; j++) {
            int c = n0 + tx*8 + j;
            Crow[c] = acc[i][j] + bias[c];
        }
    }
}

// ---------------- flash attention: 128 queries x 128 keys per block (fp32) ----------------
#define FL_SMEM_FLOATS (8192 + 16896 + 8192)
#define FL_SMEM_BYTES (FL_SMEM_FLOATS * 4)

__global__ __launch_bounds__(256) void flash_kernel() {
    extern __shared__ __align__(16) float sm[];
    float* sQ  = sm;
    float* sKP = sm + 8192;
    float* sV  = sm + 8192 + 16896;

    int tid = threadIdx.x;
    int b = blockIdx.z, h = blockIdx.y;
    int q0 = blockIdx.x * 128;
    const float* Qg = g_q + (((size_t)(b*HH + h))*NN + q0)*HD;
    const float* Kg = g_k + ((size_t)(b*HH + h))*NN*HD;
    const float* Vg = g_v + ((size_t)(b*HH + h))*NN*HD;
    const float* biasg = g_bias + (size_t)(b*HH + h)*NN;
    int ty = tid >> 4, tx = tid & 15;

    int kkld = tid & 63;
    int c4b  = tid >> 6;

    #pragma unroll
    for (int r = 0; r < 8; r++) {
        int c4 = c4b + 4*r;
        float4 v;
        v.x = Qg[(size_t)(4*c4 + 0)*HD + kkld];
        v.y = Qg[(size_t)(4*c4 + 1)*HD + kkld];
        v.z = Qg[(size_t)(4*c4 + 2)*HD + kkld];
        v.w = Qg[(size_t)(4*c4 + 3)*HD + kkld];
        *(float4*)&sQ[kkld*128 + 4*(c4 ^ (kkld & 31))] = v;
    }

    float m_run[8], l_run[8], acc[8][4];
    #pragma unroll
    for (int i = 0; i < 8; i++) {
        m_run[i] = -1e30f; l_run[i] = 0.f;
        #pragma unroll
        for (int j = 0; j < 4; j++) acc[i][j] = 0.f;
    }

    for (int c0 = 0; c0 < NN; c0 += 128) {
        #pragma unroll
        for (int r = 0; r < 8; r++) {
            int c4 = c4b + 4*r;
            float4 v;
            v.x = Kg[(size_t)(c0 + 4*c4 + 0)*HD + kkld];
            v.y = Kg[(size_t)(c0 + 4*c4 + 1)*HD + kkld];
            v.z = Kg[(size_t)(c0 + 4*c4 + 2)*HD + kkld];
            v.w = Kg[(size_t)(c0 + 4*c4 + 3)*HD + kkld];
            *(float4*)&sKP[kkld*128 + 4*(c4 ^ (kkld & 31))] = v;
        }
        #pragma unroll
        for (int r = 0; r < 8; r++) {
            int f4i = tid + 256*r;
            int c = f4i >> 4, d4 = f4i & 15;
            *(float4*)&sV[c*64 + 4*d4] =
                *(const float4*)&Vg[(size_t)(c0 + c)*HD + 4*d4];
        }
        float bv[8];
        #pragma unroll
        for (int j = 0; j < 4; j++) {
            bv[j]   = biasg[c0 + 4*tx + j];
            bv[j+4] = biasg[c0 + 64 + 4*tx + j];
        }
        __syncthreads();

        float s[8][8];
        #pragma unroll
        for (int i = 0; i < 8; i++)
            #pragma unroll
            for (int j = 0; j < 8; j++) s[i][j] = 0.f;
        #pragma unroll 4
        for (int kk = 0; kk < 64; kk++) {
            int sw = kk & 31;
            float4 q0v = *(const float4*)&sQ [kk*128 + 4*( ty       ^ sw)];
            float4 q1v = *(const float4*)&sQ [kk*128 + 4*((16 + ty) ^ sw)];
            float4 k0v = *(const float4*)&sKP[kk*128 + 4*( tx       ^ sw)];
            float4 k1v = *(const float4*)&sKP[kk*128 + 4*((16 + tx) ^ sw)];
            float qa[8] = {q0v.x, q0v.y, q0v.z, q0v.w, q1v.x, q1v.y, q1v.z, q1v.w};
            float ka[8] = {k0v.x, k0v.y, k0v.z, k0v.w, k1v.x, k1v.y, k1v.z, k1v.w};
            #pragma unroll
            for (int i = 0; i < 8; i++)
                #pragma unroll
                for (int j = 0; j < 8; j++)
                    s[i][j] = fmaf(qa[i], ka[j], s[i][j]);
        }

        float ef[8];
        #pragma unroll
        for (int i = 0; i < 8; i++) {
            float rm = -1e30f;
            #pragma unroll
            for (int j = 0; j < 8; j++) {
                s[i][j] = fmaf(s[i][j], SCALE, bv[j]);
                rm = fmaxf(rm, s[i][j]);
            }
            #pragma unroll
            for (int msk = 8; msk >= 1; msk >>= 1)
                rm = fmaxf(rm, __shfl_xor_sync(0xffffffffu, rm, msk));
            float m_new = fmaxf(m_run[i], rm);
            ef[i] = __expf(m_run[i] - m_new);
            float rs = 0.f;
            #pragma unroll
            for (int j = 0; j < 8; j++) {
                s[i][j] = __expf(s[i][j] - m_new);
                rs += s[i][j];
            }
            #pragma unroll
            for (int msk = 8; msk >= 1; msk >>= 1)
                rs += __shfl_xor_sync(0xffffffffu, rs, msk);
            l_run[i] = l_run[i]*ef[i] + rs;
            m_run[i] = m_new;
            #pragma unroll
            for (int j = 0; j < 4; j++) acc[i][j] *= ef[i];
        }

        __syncthreads();
        #pragma unroll
        for (int i = 0; i < 8; i++) {
            int q = (i < 4) ? (4*ty + i) : (64 + 4*ty + (i - 4));
            float4 lo = make_float4(s[i][0], s[i][1], s[i][2], s[i][3]);
            float4 hi = make_float4(s[i][4], s[i][5], s[i][6], s[i][7]);
            *(float4*)&sKP[q*132 + 4*tx]      = lo;
            *(float4*)&sKP[q*132 + 64 + 4*tx] = hi;
        }
        __syncthreads();

        #pragma unroll 2
        for (int c4 = 0; c4 < 32; c4++) {
            float4 v0 = *(const float4*)&sV[(4*c4 + 0)*64 + 4*tx];
            float4 v1 = *(const float4*)&sV[(4*c4 + 1)*64 + 4*tx];
            float4 v2 = *(const float4*)&sV[(4*c4 + 2)*64 + 4*tx];
            float4 v3 = *(const float4*)&sV[(4*c4 + 3)*64 + 4*tx];
            #pragma unroll
            for (int i = 0; i < 8; i++) {
                int q = (i < 4) ? (4*ty + i) : (64 + 4*ty + (i - 4));
                float4 pv = *(const float4*)&sKP[q*132 + 4*c4];
                acc[i][0] = fmaf(pv.x, v0.x, acc[i][0]);
                acc[i][1] = fmaf(pv.x, v0.y, acc[i][1]);
                acc[i][2] = fmaf(pv.x, v0.z, acc[i][2]);
                acc[i][3] = fmaf(pv.x, v0.w, acc[i][3]);
                acc[i][0] = fmaf(pv.y, v1.x, acc[i][0]);
                acc[i][1] = fmaf(pv.y, v1.y, acc[i][1]);
                acc[i][2] = fmaf(pv.y, v1.z, acc[i][2]);
                acc[i][3] = fmaf(pv.y, v1.w, acc[i][3]);
                acc[i][0] = fmaf(pv.z, v2.x, acc[i][0]);
                acc[i][1] = fmaf(pv.z, v2.y, acc[i][1]);
                acc[i][2] = fmaf(pv.z, v2.z, acc[i][2]);
                acc[i][3] = fmaf(pv.z, v2.w, acc[i][3]);
                acc[i][0] = fmaf(pv.w, v3.x, acc[i][0]);
                acc[i][1] = fmaf(pv.w, v3.y, acc[i][1]);
                acc[i][2] = fmaf(pv.w, v3.z, acc[i][2]);
                acc[i][3] = fmaf(pv.w, v3.w, acc[i][3]);
            }
        }
        __syncthreads();
    }

    #pragma unroll
    for (int i = 0; i < 8; i++) {
        int q = (i < 4) ? (4*ty + i) : (64 + 4*ty + (i - 4));
        float inv = 1.0f / l_run[i];
        float4 o;
        o.x = acc[i][0]*inv; o.y = acc[i][1]*inv;
        o.z = acc[i][2]*inv; o.w = acc[i][3]*inv;
        *(float4*)&g_attnout[((size_t)b*NN + q0 + q)*DD + h*HD + 4*tx] = o;
    }
}

// ---------------- launch ----------------
extern "C" void kernel_launch(void* const* d_in, const int* in_sizes, int n_in,
                              void* d_out, int out_size) {
    const float* x        = (const float*)d_in[0];
    const float* coverage = (const float*)d_in[1];
    const float* w_qkv    = (const float*)d_in[2];
    const float* w_out    = (const float*)d_in[3];
    const float* b_out    = (const float*)d_in[4];
    const float* w_ce1    = (const float*)d_in[5];
    const float* b_ce1    = (const float*)d_in[6];
    const float* w_ce2    = (const float*)d_in[7];
    const float* b_ce2    = (const float*)d_in[8];
    const float* w_fg1    = (const float*)d_in[9];
    const float* b_fg1    = (const float*)d_in[10];
    const float* w_fg2    = (const float*)d_in[11];
    const float* b_fg2    = (const float*)d_in[12];
    float* out = (float*)d_out;

    cudaFuncSetAttribute(flash_kernel,
        cudaFuncAttributeMaxDynamicSharedMemorySize, FL_SMEM_BYTES);

    // pooled gate path
    zero_pooled_kernel<<<(BB*DD + 255)/256, 256>>>();
    pool_kernel<<<dim3(DD/256, BB, NN/128), 256>>>(x);
    gate_kernel<<<BB, 256>>>(w_fg1, b_fg1, w_fg2, b_fg2);
    // coverage bias (needs gate)
    cov_kernel3<<<dim3(NN/8, BB), 256>>>(coverage, w_ce1, b_ce1, w_ce2, b_ce2);

    // bf16 hi/lo conversions (QKV inputs only)
    split_kernel<<<(BB*NN*DD/4 + 255)/256, 256>>>(x, g_xa_hi, g_xa_lo);
    tsplit_kernel<<<dim3(3*DD/32, DD/32), dim3(32, 8)>>>(w_qkv, g_wqt_hi, g_wqt_lo, DD, 3*DD);

    // QKV projection (tensor cores, mma.sync, direct-LDS fragments)
    hgemm_qkv<<<dim3(3*DD/128, BB*NN/128), 256>>>(
        g_xa_hi, g_xa_lo, g_wqt_hi, g_wqt_lo);

    // fused attention (fp32)
    flash_kernel<<<dim3(NN/128, HH, BB), 256, FL_SMEM_BYTES>>>();

    // output projection (fp32, known-good)
    sgemm_out<<<dim3(DD/128, BB*NN/128), 256>>>(w_out, out, b_out);
}